// round 16
// baseline (speedup 1.0000x reference)
#include <cuda_runtime.h>
#include <math_constants.h>

#define N_NODES 50000
#define N_EDGES 800000
#define ET (N_EDGES + N_NODES)   // + self loops; ET % 4 == 0, N_EDGES % 4 == 0
#define C 64
#define F_IN 128
#define NEG_SLOPE 0.2f
#define NEG_BIG (-1e30f)

#define GB2 ((N_NODES + 127) / 128)       // 391 gemm tiles (128 nodes each)
#define GBM ((N_NODES + 63) / 64)         // 782 mlp tiles
#define HB2 512                           // grid-stride hist blocks
#define ET4 (ET / 4)                      // 212500 int4 edge groups

// ---------------- scratch (static device globals; no allocation) ----------------
__device__ int   g_cnt[N_NODES];                 // zero-init at load; re-zeroed by scan_all
__device__ int   g_rank[ET];                     // packed (rank<<17)|dst
__device__ int   g_rowoff[N_NODES + 1];
__device__ int   g_csrc[ET];                     // CSR: src sorted by dst
__device__ float g_h[(size_t)N_NODES * C];
__device__ float g_out0[(size_t)N_NODES * C];
__device__ float g_out1[(size_t)N_NODES * C];
__device__ float g_ssrc[N_NODES];
__device__ float g_sdst[N_NODES];

__device__ __forceinline__ float leaky(float e) {
    return (e > 0.0f) ? e : NEG_SLOPE * e;
}

// ---------------- GEMM tile body: 128 nodes x 64 channels, K-chunked staging ----------------
// h = X @ W; s_src = h.att_src; s_dst = h.att_dst
// 256 threads = 16(tx: 4-channel groups) x 16(ty: 8-row groups); 8x4 per thread.
template <int K, bool X_FROM_OUT0>
__device__ __forceinline__ void gemm_body(int tile,
                                          const float* __restrict__ Xext,
                                          const float* __restrict__ W,
                                          const float* __restrict__ av_s,
                                          const float* __restrict__ av_d,
                                          float* sm) {
    const int KC = 64;                             // K-chunk size
    const int XPITCH = KC + 2;                     // float2-aligned row stride
    float (*Xs)[XPITCH] = (float (*)[XPITCH])sm;   // 128 x 66
    float* Bsm = sm + 128 * XPITCH;                // K x 64 (full W)

    const float* X = X_FROM_OUT0 ? g_out0 : Xext;
    int tid = threadIdx.x;
    int tx = tid & 15;                 // channels tx*4 .. tx*4+3
    int ty = tid >> 4;                 // rows ty*8 .. ty*8+7
    int nodeBase = tile * 128;

    for (int idx = tid; idx < K * C; idx += 256)
        Bsm[idx] = W[idx];

    float acc[8][4] = {};
#pragma unroll
    for (int kc = 0; kc < K; kc += KC) {
        __syncthreads();               // protect Xs reuse (and Bsm load on first iter)
        for (int idx = tid; idx < 128 * KC; idx += 256) {
            int r = idx / KC, k = idx - r * KC;
            int n = nodeBase + r;
            Xs[r][k] = (n < N_NODES) ? X[(size_t)n * K + kc + k] : 0.0f;
        }
        __syncthreads();
        for (int k = 0; k < KC; k += 2) {
            float4 b0 = *(const float4*)&Bsm[(kc + k) * C + tx * 4];
            float4 b1 = *(const float4*)&Bsm[(kc + k + 1) * C + tx * 4];
#pragma unroll
            for (int i = 0; i < 8; i++) {
                float2 a = *(const float2*)&Xs[ty * 8 + i][k];
                acc[i][0] = fmaf(a.x, b0.x, fmaf(a.y, b1.x, acc[i][0]));
                acc[i][1] = fmaf(a.x, b0.y, fmaf(a.y, b1.y, acc[i][1]));
                acc[i][2] = fmaf(a.x, b0.z, fmaf(a.y, b1.z, acc[i][2]));
                acc[i][3] = fmaf(a.x, b0.w, fmaf(a.y, b1.w, acc[i][3]));
            }
        }
    }

#pragma unroll
    for (int i = 0; i < 8; i++) {
        int n = nodeBase + ty * 8 + i;
        if (n < N_NODES) {
            float4 v = make_float4(acc[i][0], acc[i][1], acc[i][2], acc[i][3]);
            *(float4*)&g_h[(size_t)n * C + tx * 4] = v;
        }
    }

    float4 as4 = *(const float4*)&av_s[tx * 4];
    float4 ad4 = *(const float4*)&av_d[tx * 4];
#pragma unroll
    for (int i = 0; i < 8; i++) {
        float p1 = acc[i][0] * as4.x + acc[i][1] * as4.y
                 + acc[i][2] * as4.z + acc[i][3] * as4.w;
        float p2 = acc[i][0] * ad4.x + acc[i][1] * ad4.y
                 + acc[i][2] * ad4.z + acc[i][3] * ad4.w;
#pragma unroll
        for (int o = 8; o > 0; o >>= 1) {
            p1 += __shfl_down_sync(0xffffffffu, p1, o, 16);
            p2 += __shfl_down_sync(0xffffffffu, p2, o, 16);
        }
        int n = nodeBase + ty * 8 + i;
        if (tx == 0 && n < N_NODES) { g_ssrc[n] = p1; g_sdst[n] = p2; }
    }
}

// ---------------- K1: gemm0 (blocks < GB2)  ||  grid-stride int4 histogram (rest) ----------------
__global__ __launch_bounds__(256)
void fused_gemm0_hist(const float* __restrict__ x,
                      const float* __restrict__ W,
                      const float* __restrict__ av_s,
                      const float* __restrict__ av_d,
                      const int* __restrict__ ei) {
    extern __shared__ float sm[];
    if (blockIdx.x < GB2) {
        gemm_body<F_IN, false>(blockIdx.x, x, W, av_s, av_d, sm);
    } else {
        // int4 over edge groups; each group is uniformly loop-edges or self-loops
        const int4* dst4 = (const int4*)(ei + N_EDGES);
        int4* rank4 = (int4*)g_rank;
        int start = (blockIdx.x - GB2) * 256 + threadIdx.x;
        for (int g = start; g < ET4; g += HB2 * 256) {
            int i = g * 4;
            int4 d;
            if (i < N_EDGES) d = dst4[g];
            else { int n = i - N_EDGES; d = make_int4(n, n + 1, n + 2, n + 3); }
            int4 pk;
            pk.x = (atomicAdd(&g_cnt[d.x], 1) << 17) | d.x;
            pk.y = (atomicAdd(&g_cnt[d.y], 1) << 17) | d.y;
            pk.z = (atomicAdd(&g_cnt[d.z], 1) << 17) | d.z;
            pk.w = (atomicAdd(&g_cnt[d.w], 1) << 17) | d.w;
            rank4[g] = pk;
        }
    }
}

// ---------------- K2: single-block full prefix scan (int4); re-zeroes g_cnt ----------------
__global__ void scan_all() {
    __shared__ int wsums[32];
    __shared__ int s_carry;
    const int NI4 = N_NODES / 4;           // 12500 (N_NODES % 4 == 0)
    int t = threadIdx.x;
    int lane = t & 31, w = t >> 5;
    if (t == 0) { s_carry = 0; g_rowoff[0] = 0; }
    __syncthreads();
    int4* cnt4 = (int4*)g_cnt;
    for (int base = 0; base < NI4; base += 1024) {
        int i4 = base + t;
        int4 v = (i4 < NI4) ? cnt4[i4] : make_int4(0, 0, 0, 0);
        if (i4 < NI4) cnt4[i4] = make_int4(0, 0, 0, 0);
        int s0 = v.x;
        int s1 = s0 + v.y;
        int s2 = s1 + v.z;
        int s3 = s2 + v.w;
        int xv = s3;
#pragma unroll
        for (int o = 1; o < 32; o <<= 1) {
            int y = __shfl_up_sync(0xffffffffu, xv, o);
            if (lane >= o) xv += y;
        }
        if (lane == 31) wsums[w] = xv;
        __syncthreads();
        if (w == 0) {
            int y = wsums[lane];
#pragma unroll
            for (int o = 1; o < 32; o <<= 1) {
                int z = __shfl_up_sync(0xffffffffu, y, o);
                if (lane >= o) y += z;
            }
            wsums[lane] = y;
        }
        __syncthreads();
        int excl = (xv - s3) + (w > 0 ? wsums[w - 1] : 0) + s_carry;
        if (i4 < NI4) {
            int i = i4 * 4;
            g_rowoff[i + 1] = excl + s0;
            g_rowoff[i + 2] = excl + s1;
            g_rowoff[i + 3] = excl + s2;
            g_rowoff[i + 4] = excl + s3;
        }
        __syncthreads();
        if (t == 0) s_carry += wsums[31];
        __syncthreads();
    }
}

// ---------------- K3: CSR fill, int4 (no atomics; (rank,dst) packed) ----------------
__global__ void csr_fill(const int* __restrict__ ei) {
    int g = blockIdx.x * blockDim.x + threadIdx.x;
    if (g >= ET4) return;
    int i = g * 4;
    const int4* src4 = (const int4*)ei;
    int4 s;
    if (i < N_EDGES) s = src4[g];
    else { int n = i - N_EDGES; s = make_int4(n, n + 1, n + 2, n + 3); }
    int4 pk = ((const int4*)g_rank)[g];
    g_csrc[g_rowoff[pk.x & 0x1FFFF] + (pk.x >> 17)] = s.x;
    g_csrc[g_rowoff[pk.y & 0x1FFFF] + (pk.y >> 17)] = s.y;
    g_csrc[g_rowoff[pk.z & 0x1FFFF] + (pk.z >> 17)] = s.z;
    g_csrc[g_rowoff[pk.w & 0x1FFFF] + (pk.w >> 17)] = s.w;
}

// ---------------- standalone gemm (layer 1) ----------------
template <int K, bool X_FROM_OUT0>
__global__ __launch_bounds__(256)
void gemm_att2(const float* __restrict__ Xext,
               const float* __restrict__ W,
               const float* __restrict__ av_s,
               const float* __restrict__ av_d) {
    extern __shared__ float sm[];
    gemm_body<K, X_FROM_OUT0>(blockIdx.x, Xext, W, av_s, av_d, sm);
}

// ---------------- CSR pull aggregation, exact softmax ----------------
// 2 nodes per warp; 16-lane group per node; lane owns 4 channels as float4.
template <bool SECOND>
__global__ __launch_bounds__(256, 6)
void aggregate(const float* __restrict__ bias) {
    __shared__ int2 stage[8][2][32];
    int tid = threadIdx.x;
    int lane = tid & 31;
    int half = lane >> 4;          // which node of the pair
    int sl = lane & 15;            // sub-lane: channel group
    int wslot = tid >> 5;
    int d = ((blockIdx.x * blockDim.x + tid) >> 5) * 2 + half;
    if (d >= N_NODES) return;
    unsigned gmask = 0xFFFFu << (half << 4);

    int beg = g_rowoff[d], end = g_rowoff[d + 1];
    int deg = end - beg;
    float sd = g_sdst[d];
    const float4* __restrict__ hp4 = (const float4*)g_h;   // 16 float4 per row
    float4 a = make_float4(0.0f, 0.0f, 0.0f, 0.0f);

    if (deg <= 32) {
        // lane sl loads edges sl and sl+16
        int s0 = 0, s1 = 0;
        float e0 = NEG_BIG, e1 = NEG_BIG;
        if (sl < deg)      { s0 = g_csrc[beg + sl];      e0 = leaky(g_ssrc[s0] + sd); }
        if (sl + 16 < deg) { s1 = g_csrc[beg + sl + 16]; e1 = leaky(g_ssrc[s1] + sd); }
        float ml = fmaxf(e0, e1);
        float dl = 0.0f;
        if (sl < deg)      dl += __expf(e0 - ml);
        if (sl + 16 < deg) dl += __expf(e1 - ml);
#pragma unroll
        for (int o = 8; o > 0; o >>= 1) {                  // 16-lane butterfly
            float mo = __shfl_xor_sync(0xffffffffu, ml, o);
            float dn = __shfl_xor_sync(0xffffffffu, dl, o);
            float mn = fmaxf(ml, mo);
            dl = dl * __expf(ml - mn) + dn * __expf(mo - mn);
            ml = mn;
        }
        float inv = 1.0f / dl;
        float al0 = (sl < deg)      ? __expf(e0 - ml) * inv : 0.0f;
        float al1 = (sl + 16 < deg) ? __expf(e1 - ml) * inv : 0.0f;
        stage[wslot][half][sl]      = make_int2(s0, __float_as_int(al0));
        stage[wslot][half][sl + 16] = make_int2(s1, __float_as_int(al1));
        __syncwarp(gmask);
#pragma unroll 4
        for (int j = 0; j < deg; j++) {
            int2 p = stage[wslot][half][j];        // LDS.64 broadcast within group
            float4 h = hp4[(size_t)p.x * 16 + sl]; // LDG.128 gather
            float wj = __int_as_float(p.y);
            a.x = fmaf(wj, h.x, a.x);
            a.y = fmaf(wj, h.y, a.y);
            a.z = fmaf(wj, h.z, a.z);
            a.w = fmaf(wj, h.w, a.w);
        }
    } else {
        // phase 1: strided online (max, den) over the 16-lane group
        float ml = NEG_BIG, dl = 0.0f;
        for (int j = beg + sl; j < end; j += 16) {
            float e = leaky(g_ssrc[g_csrc[j]] + sd);
            float mn = fmaxf(ml, e);
            dl = dl * __expf(ml - mn) + __expf(e - mn);
            ml = mn;
        }
#pragma unroll
        for (int o = 8; o > 0; o >>= 1) {
            float mo = __shfl_xor_sync(0xffffffffu, ml, o);
            float dn = __shfl_xor_sync(0xffffffffu, dl, o);
            float mn = fmaxf(ml, mo);
            dl = dl * __expf(ml - mn) + dn * __expf(mo - mn);
            ml = mn;
        }
        float m = ml;
        float inv = 1.0f / dl;
        // phase 2: chunks of 32 edges, staged
        for (int base = beg; base < end; base += 32) {
            int cnt = min(32, end - base);
            int s0 = 0, s1 = 0;
            float al0 = 0.0f, al1 = 0.0f;
            if (sl < cnt) {
                s0 = g_csrc[base + sl];
                al0 = __expf(leaky(g_ssrc[s0] + sd) - m) * inv;
            }
            if (sl + 16 < cnt) {
                s1 = g_csrc[base + sl + 16];
                al1 = __expf(leaky(g_ssrc[s1] + sd) - m) * inv;
            }
            stage[wslot][half][sl]      = make_int2(s0, __float_as_int(al0));
            stage[wslot][half][sl + 16] = make_int2(s1, __float_as_int(al1));
            __syncwarp(gmask);
#pragma unroll 4
            for (int j = 0; j < cnt; j++) {
                int2 p = stage[wslot][half][j];
                float4 h = hp4[(size_t)p.x * 16 + sl];
                float wj = __int_as_float(p.y);
                a.x = fmaf(wj, h.x, a.x);
                a.y = fmaf(wj, h.y, a.y);
                a.z = fmaf(wj, h.z, a.z);
                a.w = fmaf(wj, h.w, a.w);
            }
            __syncwarp(gmask);
        }
    }
    const float4* bp = (const float4*)bias;
    float4 bb = bp[sl];
    float4* o = (float4*)((SECOND ? g_out1 : g_out0) + (size_t)d * C);
    o[sl] = make_float4(a.x + bb.x, a.y + bb.y, a.z + bb.z, a.w + bb.w);
}

// ---------------- MLP head: tiled GEMM 64->64 (relu) -> 64->10 (relu) ----------------
__global__ __launch_bounds__(256, 6)
void mlp_head2(const float* __restrict__ W0, const float* __restrict__ b0,
               const float* __restrict__ W1, const float* __restrict__ b1,
               float* __restrict__ out) {
    __shared__ float Ys[64][C + 1];
    __shared__ float W0s[C * C];
    __shared__ float W1s[C * 10];
    __shared__ float b0s[C], b1s[10];

    int tid = threadIdx.x;
    int tx = tid & 15;
    int ty = tid >> 4;
    int nodeBase = blockIdx.x * 64;

    for (int idx = tid; idx < 64 * C; idx += 256) {
        int r = idx >> 6, k = idx & 63;
        int n = nodeBase + r;
        Ys[r][k] = (n < N_NODES) ? g_out1[(size_t)n * C + k] : 0.0f;
    }
    for (int idx = tid; idx < C * C; idx += 256) W0s[idx] = W0[idx];
    for (int idx = tid; idx < C * 10; idx += 256) W1s[idx] = W1[idx];
    if (tid < C) b0s[tid] = b0[tid];
    if (tid < 10) b1s[tid] = b1[tid];
    __syncthreads();

    float acc[4][4];
#pragma unroll
    for (int i = 0; i < 4; i++) {
        float bb = b0s[tx * 4 + i];
        acc[0][i] = bb; acc[1][i] = bb; acc[2][i] = bb; acc[3][i] = bb;
    }
#pragma unroll 4
    for (int k = 0; k < C; k++) {
        float4 b = *(const float4*)&W0s[k * C + tx * 4];
        float a0 = Ys[ty * 4 + 0][k];
        float a1 = Ys[ty * 4 + 1][k];
        float a2 = Ys[ty * 4 + 2][k];
        float a3 = Ys[ty * 4 + 3][k];
        acc[0][0] = fmaf(a0, b.x, acc[0][0]); acc[0][1] = fmaf(a0, b.y, acc[0][1]);
        acc[0][2] = fmaf(a0, b.z, acc[0][2]); acc[0][3] = fmaf(a0, b.w, acc[0][3]);
        acc[1][0] = fmaf(a1, b.x, acc[1][0]); acc[1][1] = fmaf(a1, b.y, acc[1][1]);
        acc[1][2] = fmaf(a1, b.z, acc[1][2]); acc[1][3] = fmaf(a1, b.w, acc[1][3]);
        acc[2][0] = fmaf(a2, b.x, acc[2][0]); acc[2][1] = fmaf(a2, b.y, acc[2][1]);
        acc[2][2] = fmaf(a2, b.z, acc[2][2]); acc[2][3] = fmaf(a2, b.w, acc[2][3]);
        acc[3][0] = fmaf(a3, b.x, acc[3][0]); acc[3][1] = fmaf(a3, b.y, acc[3][1]);
        acc[3][2] = fmaf(a3, b.z, acc[3][2]); acc[3][3] = fmaf(a3, b.w, acc[3][3]);
    }
    __syncthreads();
#pragma unroll
    for (int mi = 0; mi < 4; mi++) {
        int r = ty * 4 + mi;
        Ys[r][tx * 4 + 0] = fmaxf(acc[mi][0], 0.0f);
        Ys[r][tx * 4 + 1] = fmaxf(acc[mi][1], 0.0f);
        Ys[r][tx * 4 + 2] = fmaxf(acc[mi][2], 0.0f);
        Ys[r][tx * 4 + 3] = fmaxf(acc[mi][3], 0.0f);
    }
    __syncthreads();

    for (int idx = tid; idx < 640; idx += 256) {
        int r = idx / 10, c = idx - r * 10;
        int n = nodeBase + r;
        if (n >= N_NODES) continue;
        float a = b1s[c];
#pragma unroll 8
        for (int k = 0; k < C; k++)
            a = fmaf(Ys[r][k], W1s[k * 10 + c], a);
        out[n * 10 + c] = fmaxf(a, 0.0f);
    }
}

// ---------------- launch ----------------

extern "C" void kernel_launch(void* const* d_in, const int* in_sizes, int n_in,
                              void* d_out, int out_size) {
    const float* x     = (const float*)d_in[0];
    const int*   ei    = (const int*)d_in[1];
    const float* g0_W  = (const float*)d_in[2];
    const float* g0_as = (const float*)d_in[3];
    const float* g0_ad = (const float*)d_in[4];
    const float* g0_b  = (const float*)d_in[5];
    const float* g1_W  = (const float*)d_in[6];
    const float* g1_as = (const float*)d_in[7];
    const float* g1_ad = (const float*)d_in[8];
    const float* g1_b  = (const float*)d_in[9];
    const float* l0_W  = (const float*)d_in[10];
    const float* l0_b  = (const float*)d_in[11];
    const float* l1_W  = (const float*)d_in[12];
    const float* l1_b  = (const float*)d_in[13];
    float* out = (float*)d_out;

    const int TB = 256;
    const int fb = (ET4 + TB - 1) / TB;                        // int4 fill blocks -> 831
    const int ab = (((N_NODES + 1) / 2) * 32 + TB - 1) / TB;   // 2 nodes/warp -> 3125

    const int smem0 = (128 * 66 + F_IN * C) * (int)sizeof(float);  // ~66.5 KB
    const int smem1 = (128 * 66 + C * C) * (int)sizeof(float);     // ~50.2 KB
    cudaFuncSetAttribute(fused_gemm0_hist,
                         cudaFuncAttributeMaxDynamicSharedMemorySize, smem0);
    cudaFuncSetAttribute(gemm_att2<C, true>,
                         cudaFuncAttributeMaxDynamicSharedMemorySize, smem1);

    // K1: gemm layer-0 || grid-stride int4 histogram + packed ranks
    fused_gemm0_hist<<<GB2 + HB2, TB, smem0>>>(x, g0_W, g0_as, g0_ad, ei);
    // K2: full prefix scan (single block, int4); re-zeroes counters
    scan_all<<<1, 1024>>>();
    // K3: CSR fill (atomic-free, int4 packed rank+dst)
    csr_fill<<<fb, TB>>>(ei);
    // K4: aggregate layer 0
    aggregate<false><<<ab, TB>>>(g0_b);
    // K5: gemm layer 1
    gemm_att2<C, true><<<GB2, TB, smem1>>>(nullptr, g1_W, g1_as, g1_ad);
    // K6: aggregate layer 1
    aggregate<true><<<ab, TB>>>(g1_b);
    // K7: MLP head
    mlp_head2<<<GBM, TB>>>(l0_W, l0_b, l1_W, l1_b, out);
}

// round 17
// speedup vs baseline: 1.0231x; 1.0231x over previous
#include <cuda_runtime.h>
#include <math_constants.h>

#define N_NODES 50000
#define N_EDGES 800000
#define ET (N_EDGES + N_NODES)   // + self loops
#define C 64
#define F_IN 128
#define NEG_SLOPE 0.2f
#define NEG_BIG (-1e30f)

#define GB2 ((N_NODES + 127) / 128)       // 391 gemm tiles (128 nodes each)
#define GBM ((N_NODES + 63) / 64)         // 782 mlp tiles
#define HB2 512                           // grid-stride hist blocks

// ---------------- scratch (static device globals; no allocation) ----------------
__device__ int   g_cnt[N_NODES];                 // zero-init at load; re-zeroed by scan_all
__device__ int   g_rank[ET];                     // packed (rank<<17)|dst
__device__ int   g_rowoff[N_NODES + 1];
__device__ int   g_csrc[ET];                     // CSR: src sorted by dst
__device__ float g_h[(size_t)N_NODES * C];
__device__ float g_out0[(size_t)N_NODES * C];
__device__ float g_out1[(size_t)N_NODES * C];
__device__ float g_ssrc[N_NODES];
__device__ float g_sdst[N_NODES];

__device__ __forceinline__ float leaky(float e) {
    return (e > 0.0f) ? e : NEG_SLOPE * e;
}

// ---------------- GEMM tile body: 128 nodes x 64 channels, K-chunked staging ----------------
// h = X @ W; s_src = h.att_src; s_dst = h.att_dst
// 256 threads = 16(tx: 4-channel groups) x 16(ty: 8-row groups); 8x4 per thread.
template <int K, bool X_FROM_OUT0>
__device__ __forceinline__ void gemm_body(int tile,
                                          const float* __restrict__ Xext,
                                          const float* __restrict__ W,
                                          const float* __restrict__ av_s,
                                          const float* __restrict__ av_d,
                                          float* sm) {
    const int KC = 64;                             // K-chunk size
    const int XPITCH = KC + 2;                     // float2-aligned row stride
    float (*Xs)[XPITCH] = (float (*)[XPITCH])sm;   // 128 x 66
    float* Bsm = sm + 128 * XPITCH;                // K x 64 (full W)

    const float* X = X_FROM_OUT0 ? g_out0 : Xext;
    int tid = threadIdx.x;
    int tx = tid & 15;                 // channels tx*4 .. tx*4+3
    int ty = tid >> 4;                 // rows ty*8 .. ty*8+7
    int nodeBase = tile * 128;

    for (int idx = tid; idx < K * C; idx += 256)
        Bsm[idx] = W[idx];

    float acc[8][4] = {};
#pragma unroll
    for (int kc = 0; kc < K; kc += KC) {
        __syncthreads();               // protect Xs reuse (and Bsm load on first iter)
        for (int idx = tid; idx < 128 * KC; idx += 256) {
            int r = idx / KC, k = idx - r * KC;
            int n = nodeBase + r;
            Xs[r][k] = (n < N_NODES) ? X[(size_t)n * K + kc + k] : 0.0f;
        }
        __syncthreads();
        for (int k = 0; k < KC; k += 2) {
            float4 b0 = *(const float4*)&Bsm[(kc + k) * C + tx * 4];
            float4 b1 = *(const float4*)&Bsm[(kc + k + 1) * C + tx * 4];
#pragma unroll
            for (int i = 0; i < 8; i++) {
                float2 a = *(const float2*)&Xs[ty * 8 + i][k];
                acc[i][0] = fmaf(a.x, b0.x, fmaf(a.y, b1.x, acc[i][0]));
                acc[i][1] = fmaf(a.x, b0.y, fmaf(a.y, b1.y, acc[i][1]));
                acc[i][2] = fmaf(a.x, b0.z, fmaf(a.y, b1.z, acc[i][2]));
                acc[i][3] = fmaf(a.x, b0.w, fmaf(a.y, b1.w, acc[i][3]));
            }
        }
    }

#pragma unroll
    for (int i = 0; i < 8; i++) {
        int n = nodeBase + ty * 8 + i;
        if (n < N_NODES) {
            float4 v = make_float4(acc[i][0], acc[i][1], acc[i][2], acc[i][3]);
            *(float4*)&g_h[(size_t)n * C + tx * 4] = v;
        }
    }

    float4 as4 = *(const float4*)&av_s[tx * 4];
    float4 ad4 = *(const float4*)&av_d[tx * 4];
#pragma unroll
    for (int i = 0; i < 8; i++) {
        float p1 = acc[i][0] * as4.x + acc[i][1] * as4.y
                 + acc[i][2] * as4.z + acc[i][3] * as4.w;
        float p2 = acc[i][0] * ad4.x + acc[i][1] * ad4.y
                 + acc[i][2] * ad4.z + acc[i][3] * ad4.w;
#pragma unroll
        for (int o = 8; o > 0; o >>= 1) {
            p1 += __shfl_down_sync(0xffffffffu, p1, o, 16);
            p2 += __shfl_down_sync(0xffffffffu, p2, o, 16);
        }
        int n = nodeBase + ty * 8 + i;
        if (tx == 0 && n < N_NODES) { g_ssrc[n] = p1; g_sdst[n] = p2; }
    }
}

// ---------------- K1: gemm0 (blocks < GB2)  ||  grid-stride histogram (rest) ----------------
__global__ __launch_bounds__(256)
void fused_gemm0_hist(const float* __restrict__ x,
                      const float* __restrict__ W,
                      const float* __restrict__ av_s,
                      const float* __restrict__ av_d,
                      const int* __restrict__ ei) {
    extern __shared__ float sm[];
    if (blockIdx.x < GB2) {
        gemm_body<F_IN, false>(blockIdx.x, x, W, av_s, av_d, sm);
    } else {
        int start = (blockIdx.x - GB2) * 256 + threadIdx.x;
        for (int i = start; i < ET; i += HB2 * 256) {
            int d = (i < N_EDGES) ? ei[N_EDGES + i] : (i - N_EDGES);
            int r = atomicAdd(&g_cnt[d], 1);
            g_rank[i] = (r << 17) | d;     // pack: rank (<=2^14) | dst (<2^17)
        }
    }
}

// ---------------- K2: single-block full prefix scan (int4); re-zeroes g_cnt ----------------
__global__ void scan_all() {
    __shared__ int wsums[32];
    __shared__ int s_carry;
    const int NI4 = N_NODES / 4;           // 12500 (N_NODES % 4 == 0)
    int t = threadIdx.x;
    int lane = t & 31, w = t >> 5;
    if (t == 0) { s_carry = 0; g_rowoff[0] = 0; }
    __syncthreads();
    int4* cnt4 = (int4*)g_cnt;
    for (int base = 0; base < NI4; base += 1024) {
        int i4 = base + t;
        int4 v = (i4 < NI4) ? cnt4[i4] : make_int4(0, 0, 0, 0);
        if (i4 < NI4) cnt4[i4] = make_int4(0, 0, 0, 0);
        int s0 = v.x;
        int s1 = s0 + v.y;
        int s2 = s1 + v.z;
        int s3 = s2 + v.w;
        int xv = s3;
#pragma unroll
        for (int o = 1; o < 32; o <<= 1) {
            int y = __shfl_up_sync(0xffffffffu, xv, o);
            if (lane >= o) xv += y;
        }
        if (lane == 31) wsums[w] = xv;
        __syncthreads();
        if (w == 0) {
            int y = wsums[lane];
#pragma unroll
            for (int o = 1; o < 32; o <<= 1) {
                int z = __shfl_up_sync(0xffffffffu, y, o);
                if (lane >= o) y += z;
            }
            wsums[lane] = y;
        }
        __syncthreads();
        int excl = (xv - s3) + (w > 0 ? wsums[w - 1] : 0) + s_carry;
        if (i4 < NI4) {
            int i = i4 * 4;
            g_rowoff[i + 1] = excl + s0;
            g_rowoff[i + 2] = excl + s1;
            g_rowoff[i + 3] = excl + s2;
            g_rowoff[i + 4] = excl + s3;
        }
        __syncthreads();
        if (t == 0) s_carry += wsums[31];
        __syncthreads();
    }
}

// ---------------- K3: CSR fill (no atomics; (rank,dst) packed) ----------------
__global__ void csr_fill(const int* __restrict__ ei) {
    int i = blockIdx.x * blockDim.x + threadIdx.x;
    if (i >= ET) return;
    int s = (i < N_EDGES) ? ei[i] : (i - N_EDGES);
    int pk = g_rank[i];
    int d = pk & 0x1FFFF;
    int r = pk >> 17;
    g_csrc[g_rowoff[d] + r] = s;
}

// ---------------- standalone gemm (layer 1) ----------------
template <int K, bool X_FROM_OUT0>
__global__ __launch_bounds__(256)
void gemm_att2(const float* __restrict__ Xext,
               const float* __restrict__ W,
               const float* __restrict__ av_s,
               const float* __restrict__ av_d) {
    extern __shared__ float sm[];
    gemm_body<K, X_FROM_OUT0>(blockIdx.x, Xext, W, av_s, av_d, sm);
}

// ---------------- CSR pull aggregation, exact softmax ----------------
// 2 nodes per warp; 16-lane group per node; lane owns 4 channels as float4.
template <bool SECOND>
__global__ __launch_bounds__(256, 6)
void aggregate(const float* __restrict__ bias) {
    __shared__ int2 stage[8][2][32];
    int tid = threadIdx.x;
    int lane = tid & 31;
    int half = lane >> 4;          // which node of the pair
    int sl = lane & 15;            // sub-lane: channel group
    int wslot = tid >> 5;
    int d = ((blockIdx.x * blockDim.x + tid) >> 5) * 2 + half;
    if (d >= N_NODES) return;
    unsigned gmask = 0xFFFFu << (half << 4);

    int beg = g_rowoff[d], end = g_rowoff[d + 1];
    int deg = end - beg;
    float sd = g_sdst[d];
    const float4* __restrict__ hp4 = (const float4*)g_h;   // 16 float4 per row
    float4 a = make_float4(0.0f, 0.0f, 0.0f, 0.0f);

    if (deg <= 32) {
        // lane sl loads edges sl and sl+16
        int s0 = 0, s1 = 0;
        float e0 = NEG_BIG, e1 = NEG_BIG;
        if (sl < deg)      { s0 = g_csrc[beg + sl];      e0 = leaky(g_ssrc[s0] + sd); }
        if (sl + 16 < deg) { s1 = g_csrc[beg + sl + 16]; e1 = leaky(g_ssrc[s1] + sd); }
        float ml = fmaxf(e0, e1);
        float dl = 0.0f;
        if (sl < deg)      dl += __expf(e0 - ml);
        if (sl + 16 < deg) dl += __expf(e1 - ml);
#pragma unroll
        for (int o = 8; o > 0; o >>= 1) {                  // 16-lane butterfly
            float mo = __shfl_xor_sync(0xffffffffu, ml, o);
            float dn = __shfl_xor_sync(0xffffffffu, dl, o);
            float mn = fmaxf(ml, mo);
            dl = dl * __expf(ml - mn) + dn * __expf(mo - mn);
            ml = mn;
        }
        float inv = 1.0f / dl;
        float al0 = (sl < deg)      ? __expf(e0 - ml) * inv : 0.0f;
        float al1 = (sl + 16 < deg) ? __expf(e1 - ml) * inv : 0.0f;
        stage[wslot][half][sl]      = make_int2(s0, __float_as_int(al0));
        stage[wslot][half][sl + 16] = make_int2(s1, __float_as_int(al1));
        __syncwarp(gmask);
#pragma unroll 4
        for (int j = 0; j < deg; j++) {
            int2 p = stage[wslot][half][j];        // LDS.64 broadcast within group
            float4 h = hp4[(size_t)p.x * 16 + sl]; // LDG.128 gather
            float wj = __int_as_float(p.y);
            a.x = fmaf(wj, h.x, a.x);
            a.y = fmaf(wj, h.y, a.y);
            a.z = fmaf(wj, h.z, a.z);
            a.w = fmaf(wj, h.w, a.w);
        }
    } else {
        // phase 1: strided online (max, den) over the 16-lane group
        float ml = NEG_BIG, dl = 0.0f;
        for (int j = beg + sl; j < end; j += 16) {
            float e = leaky(g_ssrc[g_csrc[j]] + sd);
            float mn = fmaxf(ml, e);
            dl = dl * __expf(ml - mn) + __expf(e - mn);
            ml = mn;
        }
#pragma unroll
        for (int o = 8; o > 0; o >>= 1) {
            float mo = __shfl_xor_sync(0xffffffffu, ml, o);
            float dn = __shfl_xor_sync(0xffffffffu, dl, o);
            float mn = fmaxf(ml, mo);
            dl = dl * __expf(ml - mn) + dn * __expf(mo - mn);
            ml = mn;
        }
        float m = ml;
        float inv = 1.0f / dl;
        // phase 2: chunks of 32 edges, staged
        for (int base = beg; base < end; base += 32) {
            int cnt = min(32, end - base);
            int s0 = 0, s1 = 0;
            float al0 = 0.0f, al1 = 0.0f;
            if (sl < cnt) {
                s0 = g_csrc[base + sl];
                al0 = __expf(leaky(g_ssrc[s0] + sd) - m) * inv;
            }
            if (sl + 16 < cnt) {
                s1 = g_csrc[base + sl + 16];
                al1 = __expf(leaky(g_ssrc[s1] + sd) - m) * inv;
            }
            stage[wslot][half][sl]      = make_int2(s0, __float_as_int(al0));
            stage[wslot][half][sl + 16] = make_int2(s1, __float_as_int(al1));
            __syncwarp(gmask);
#pragma unroll 4
            for (int j = 0; j < cnt; j++) {
                int2 p = stage[wslot][half][j];
                float4 h = hp4[(size_t)p.x * 16 + sl];
                float wj = __int_as_float(p.y);
                a.x = fmaf(wj, h.x, a.x);
                a.y = fmaf(wj, h.y, a.y);
                a.z = fmaf(wj, h.z, a.z);
                a.w = fmaf(wj, h.w, a.w);
            }
            __syncwarp(gmask);
        }
    }
    const float4* bp = (const float4*)bias;
    float4 bb = bp[sl];
    float4* o = (float4*)((SECOND ? g_out1 : g_out0) + (size_t)d * C);
    o[sl] = make_float4(a.x + bb.x, a.y + bb.y, a.z + bb.z, a.w + bb.w);
}

// ---------------- MLP head: tiled GEMM 64->64 (relu) -> 64->10 (relu) ----------------
__global__ __launch_bounds__(256, 6)
void mlp_head2(const float* __restrict__ W0, const float* __restrict__ b0,
               const float* __restrict__ W1, const float* __restrict__ b1,
               float* __restrict__ out) {
    __shared__ float Ys[64][C + 1];
    __shared__ float W0s[C * C];
    __shared__ float W1s[C * 10];
    __shared__ float b0s[C], b1s[10];

    int tid = threadIdx.x;
    int tx = tid & 15;
    int ty = tid >> 4;
    int nodeBase = blockIdx.x * 64;

    for (int idx = tid; idx < 64 * C; idx += 256) {
        int r = idx >> 6, k = idx & 63;
        int n = nodeBase + r;
        Ys[r][k] = (n < N_NODES) ? g_out1[(size_t)n * C + k] : 0.0f;
    }
    for (int idx = tid; idx < C * C; idx += 256) W0s[idx] = W0[idx];
    for (int idx = tid; idx < C * 10; idx += 256) W1s[idx] = W1[idx];
    if (tid < C) b0s[tid] = b0[tid];
    if (tid < 10) b1s[tid] = b1[tid];
    __syncthreads();

    float acc[4][4];
#pragma unroll
    for (int i = 0; i < 4; i++) {
        float bb = b0s[tx * 4 + i];
        acc[0][i] = bb; acc[1][i] = bb; acc[2][i] = bb; acc[3][i] = bb;
    }
#pragma unroll 4
    for (int k = 0; k < C; k++) {
        float4 b = *(const float4*)&W0s[k * C + tx * 4];
        float a0 = Ys[ty * 4 + 0][k];
        float a1 = Ys[ty * 4 + 1][k];
        float a2 = Ys[ty * 4 + 2][k];
        float a3 = Ys[ty * 4 + 3][k];
        acc[0][0] = fmaf(a0, b.x, acc[0][0]); acc[0][1] = fmaf(a0, b.y, acc[0][1]);
        acc[0][2] = fmaf(a0, b.z, acc[0][2]); acc[0][3] = fmaf(a0, b.w, acc[0][3]);
        acc[1][0] = fmaf(a1, b.x, acc[1][0]); acc[1][1] = fmaf(a1, b.y, acc[1][1]);
        acc[1][2] = fmaf(a1, b.z, acc[1][2]); acc[1][3] = fmaf(a1, b.w, acc[1][3]);
        acc[2][0] = fmaf(a2, b.x, acc[2][0]); acc[2][1] = fmaf(a2, b.y, acc[2][1]);
        acc[2][2] = fmaf(a2, b.z, acc[2][2]); acc[2][3] = fmaf(a2, b.w, acc[2][3]);
        acc[3][0] = fmaf(a3, b.x, acc[3][0]); acc[3][1] = fmaf(a3, b.y, acc[3][1]);
        acc[3][2] = fmaf(a3, b.z, acc[3][2]); acc[3][3] = fmaf(a3, b.w, acc[3][3]);
    }
    __syncthreads();
#pragma unroll
    for (int mi = 0; mi < 4; mi++) {
        int r = ty * 4 + mi;
        Ys[r][tx * 4 + 0] = fmaxf(acc[mi][0], 0.0f);
        Ys[r][tx * 4 + 1] = fmaxf(acc[mi][1], 0.0f);
        Ys[r][tx * 4 + 2] = fmaxf(acc[mi][2], 0.0f);
        Ys[r][tx * 4 + 3] = fmaxf(acc[mi][3], 0.0f);
    }
    __syncthreads();

    for (int idx = tid; idx < 640; idx += 256) {
        int r = idx / 10, c = idx - r * 10;
        int n = nodeBase + r;
        if (n >= N_NODES) continue;
        float a = b1s[c];
#pragma unroll 8
        for (int k = 0; k < C; k++)
            a = fmaf(Ys[r][k], W1s[k * 10 + c], a);
        out[n * 10 + c] = fmaxf(a, 0.0f);
    }
}

// ---------------- launch ----------------

extern "C" void kernel_launch(void* const* d_in, const int* in_sizes, int n_in,
                              void* d_out, int out_size) {
    const float* x     = (const float*)d_in[0];
    const int*   ei    = (const int*)d_in[1];
    const float* g0_W  = (const float*)d_in[2];
    const float* g0_as = (const float*)d_in[3];
    const float* g0_ad = (const float*)d_in[4];
    const float* g0_b  = (const float*)d_in[5];
    const float* g1_W  = (const float*)d_in[6];
    const float* g1_as = (const float*)d_in[7];
    const float* g1_ad = (const float*)d_in[8];
    const float* g1_b  = (const float*)d_in[9];
    const float* l0_W  = (const float*)d_in[10];
    const float* l0_b  = (const float*)d_in[11];
    const float* l1_W  = (const float*)d_in[12];
    const float* l1_b  = (const float*)d_in[13];
    float* out = (float*)d_out;

    const int TB = 256;
    const int eb = (ET + TB - 1) / TB;
    const int ab = (((N_NODES + 1) / 2) * 32 + TB - 1) / TB;   // 2 nodes/warp -> 3125

    const int smem0 = (128 * 66 + F_IN * C) * (int)sizeof(float);  // ~66.5 KB
    const int smem1 = (128 * 66 + C * C) * (int)sizeof(float);     // ~50.2 KB
    cudaFuncSetAttribute(fused_gemm0_hist,
                         cudaFuncAttributeMaxDynamicSharedMemorySize, smem0);
    cudaFuncSetAttribute(gemm_att2<C, true>,
                         cudaFuncAttributeMaxDynamicSharedMemorySize, smem1);

    // K1: gemm layer-0 || grid-stride degree histogram + packed ranks
    fused_gemm0_hist<<<GB2 + HB2, TB, smem0>>>(x, g0_W, g0_as, g0_ad, ei);
    // K2: full prefix scan (single block, int4); re-zeroes counters
    scan_all<<<1, 1024>>>();
    // K3: CSR fill (atomic-free, packed rank+dst)
    csr_fill<<<eb, TB>>>(ei);
    // K4: aggregate layer 0
    aggregate<false><<<ab, TB>>>(g0_b);
    // K5: gemm layer 1
    gemm_att2<C, true><<<GB2, TB, smem1>>>(nullptr, g1_W, g1_as, g1_ad);
    // K6: aggregate layer 1
    aggregate<true><<<ab, TB>>>(g1_b);
    // K7: MLP head
    mlp_head2<<<GBM, TB>>>(l0_W, l0_b, l1_W, l1_b, out);
}